// round 9
// baseline (speedup 1.0000x reference)
#include <cuda_runtime.h>
#include <cuda_fp16.h>
#include <cstdint>

// Causal attention + ALiBi, B=2 H=16 S=2048 D=128, fp32 in/out.
// Warp-level HMMA flash attention, single-pass fp16 (m16n8k16.f32.f16.f16.f32).
// R8 (resubmit after infra failure): 2 CTAs/SM (96 KB smem, launch_bounds(256,2))
// so one CTA's softmax overlaps the other's MMA phase. 2-buffer K/V ring.

constexpr int Hc = 16;
constexpr int Sc = 2048;
constexpr int Dc = 128;
constexpr int BM = 128;
constexpr int BN = 64;
constexpr int NT = 256;
constexpr int BHSD = 2 * 16 * 2048 * 128;   // 8388608

// ---- device scratch: fp16 copies (row-major, same layout as inputs) ----
__device__ __half g_qf[BHSD];
__device__ __half g_kf[BHSD];
__device__ __half g_vf[BHSD];

// ---- smem byte offsets (rows of 256B = 128 fp16, XOR-swizzled) ----
constexpr int Q_OFF = 0;           // Q [128 m][128 k] fp16 (32768 B) — staging
constexpr int KB_OFF = 32768;      // 2 bufs, 32768 B each (K +0, V +16384)
constexpr int SMEM_BYTES = 98304;  // 96 KB -> 2 CTAs/SM

typedef uint32_t u32;

__device__ __forceinline__ u32 smem_u32(const void* p) {
    u32 a;
    asm("{ .reg .u64 t; cvta.to.shared.u64 t, %1; cvt.u32.u64 %0, t; }" : "=r"(a) : "l"(p));
    return a;
}
__device__ __forceinline__ void cp16(u32 dst, const void* src) {
    asm volatile("cp.async.cg.shared.global [%0], [%1], 16;" :: "r"(dst), "l"(src));
}
__device__ __forceinline__ float ex2(float x) {
    float y; asm("ex2.approx.f32 %0, %1;" : "=f"(y) : "f"(x)); return y;
}
__device__ __forceinline__ void ldsm4(u32* r, u32 a) {
    asm volatile("ldmatrix.sync.aligned.m8n8.x4.shared.b16 {%0,%1,%2,%3}, [%4];"
                 : "=r"(r[0]), "=r"(r[1]), "=r"(r[2]), "=r"(r[3]) : "r"(a));
}
__device__ __forceinline__ void ldsm4t(u32* r, u32 a) {
    asm volatile("ldmatrix.sync.aligned.m8n8.x4.trans.shared.b16 {%0,%1,%2,%3}, [%4];"
                 : "=r"(r[0]), "=r"(r[1]), "=r"(r[2]), "=r"(r[3]) : "r"(a));
}
// Non-volatile: pure register op, ptxas may interleave freely.
__device__ __forceinline__ void mma16816(float* c, const u32* a, u32 b0, u32 b1) {
    asm("mma.sync.aligned.m16n8k16.row.col.f32.f16.f16.f32 "
        "{%0,%1,%2,%3}, {%4,%5,%6,%7}, {%8,%9}, {%0,%1,%2,%3};"
        : "+f"(c[0]), "+f"(c[1]), "+f"(c[2]), "+f"(c[3])
        : "r"(a[0]), "r"(a[1]), "r"(a[2]), "r"(a[3]), "r"(b0), "r"(b1));
}
__device__ __forceinline__ u32 packh2(float a, float b) {
    __half2 h = __floats2half2_rn(a, b);
    return *(u32*)&h;
}

// =================== conversion kernel (fp32 -> fp16) ===================
__global__ void __launch_bounds__(256) cvt_kernel(const float* __restrict__ q,
                                                  const float* __restrict__ k,
                                                  const float* __restrict__ v) {
    int t = blockIdx.x * 256 + threadIdx.x;      // 24576*256 = 3 * 2097152 float4s
    const float* src;
    __half* dst;
    int i;
    if (t < 2097152)      { src = q; dst = g_qf; i = t; }
    else if (t < 4194304) { src = k; dst = g_kf; i = t - 2097152; }
    else                  { src = v; dst = g_vf; i = t - 4194304; }
    float4 x = ((const float4*)src)[i];
    uint2 w;
    w.x = packh2(x.x, x.y);
    w.y = packh2(x.z, x.w);
    ((uint2*)dst)[i] = w;
}

// =================== main attention kernel ===================

// cp.async loader for one K/V fp16 tile: 64 rows x 128 fp16 each.
__device__ __forceinline__ void load_kv(const __half* kf, const __half* vf,
                                        u32 dst, int tid) {
#pragma unroll
    for (int i = 0; i < 4; ++i) {
        const int idx = i * 256 + tid;
        const int row = idx >> 4, g = idx & 15;
        const u32 off = row * 256 + (((u32)(g ^ (row & 7))) << 4);
        const int so = row * Dc + g * 8;
        cp16(dst + off, kf + so);
        cp16(dst + 16384 + off, vf + so);
    }
}

__global__ void __launch_bounds__(NT, 2)
attn_hmma_kernel(float* __restrict__ gout) {
    extern __shared__ char smc[];
    const u32 sb = smem_u32(smc);
    const int tid = threadIdx.x;
    const int lane = tid & 31;
    const int w = tid >> 5;

    const int bh = blockIdx.x;
    const int qtile = 15 - (int)blockIdx.y;   // heavy tiles first
    const int h = bh & (Hc - 1);
    const int q0 = qtile * BM;
    const int jmax = 2 * qtile + 1;           // >= 1 always

    const float LOG2E = 1.4426950408889634f;
    const float kscale2 = LOG2E * 0.08838834764831845f;   // log2e / sqrt(128)
    const float slope2 = exp2f(-0.5f * (float)(h + 1)) * LOG2E;

    const size_t bhoff = (size_t)bh * Sc * Dc;

    // ---- prologue: stage Q (swizzled) + K/V tile 0 ----
    {
        const __half* qf = g_qf + bhoff + (size_t)q0 * Dc;
#pragma unroll
        for (int i = 0; i < 8; ++i) {
            const int idx = i * 256 + tid;
            const int row = idx >> 4, g = idx & 15;
            const u32 off = row * 256 + (((u32)(g ^ (row & 7))) << 4);
            cp16(sb + Q_OFF + off, qf + row * Dc + g * 8);
        }
        load_kv(g_kf + bhoff, g_vf + bhoff, sb + KB_OFF, tid);
    }
    asm volatile("cp.async.commit_group;");
    asm volatile("cp.async.wait_group 0;");
    __syncthreads();

    // ---- per-lane ldmatrix address pieces ----
    const u32 xsw = ((u32)(lane & 7)) << 4;
    const int qrow = 16 * w + (lane & 7) + ((lane >> 3) & 1) * 8;
    const u32 qA = sb + Q_OFF + qrow * 256 + (((u32)(lane >> 4)) << 4);
    const int krow = (lane & 7) + ((lane >> 4) & 1) * 8;
    const u32 kAoff = krow * 256 + (((u32)((lane >> 3) & 1)) << 4);
    const int vrow = (lane & 7) + ((lane >> 3) & 1) * 8;
    const u32 vAoff = vrow * 256 + (((u32)(lane >> 4)) << 4);

    // ---- hoist Q fragments to registers ----
    u32 qf[8][4];
#pragma unroll
    for (int ks = 0; ks < 8; ++ks) ldsm4(qf[ks], (qA + ks * 32) ^ xsw);

    // ---- running state ----
    float O[16][4];
#pragma unroll
    for (int nt = 0; nt < 16; ++nt)
#pragma unroll
        for (int e = 0; e < 4; ++e) O[nt][e] = 0.f;
    float mrun0 = -1e30f, mrun1 = -1e30f, lrun0 = 0.f, lrun1 = 0.f;

    const int rowg0 = q0 + 16 * w + (lane >> 2);
    const int rowg1 = rowg0 + 8;
    const float rb0 = slope2 * (float)rowg0;
    const float d8 = slope2 * 8.0f;
    const float cstep = slope2 * (float)(2 * (lane & 3));
    float snt[8];
#pragma unroll
    for (int nt = 0; nt < 8; ++nt) snt[nt] = slope2 * (float)(8 * nt);

    for (int j = 0; j <= jmax; ++j) {
        const int p = j & 1;

        __syncthreads();   // prior-iter reads of buffer p^1 complete
        if (j < jmax) {
            const size_t toff = bhoff + (size_t)(j + 1) * BN * Dc;
            load_kv(g_kf + toff, g_vf + toff, sb + KB_OFF + (p ^ 1) * 32768, tid);
        }
        asm volatile("cp.async.commit_group;");
        asm volatile("cp.async.wait_group 1;");   // buffer p's group complete
        __syncthreads();                           // publish buffer p

        // ---- S = Q K^T, np-outer; scale/alibi/max fused per chain ----
        float S[8][4];
        const u32 kA = sb + KB_OFF + p * 32768 + kAoff;
        u32 kb8[8];
#pragma unroll
        for (int ks = 0; ks < 8; ++ks) kb8[ks] = (kA + ks * 32) ^ xsw;

        const bool interior = (j < jmax - 1);
        const float cj = slope2 * (float)(j * 64) + cstep;
        float m0 = -1e30f, m1 = -1e30f;

#pragma unroll
        for (int np = 0; np < 4; ++np) {
            float* S0 = S[2 * np];
            float* S1 = S[2 * np + 1];
#pragma unroll
            for (int e = 0; e < 4; ++e) { S0[e] = 0.f; S1[e] = 0.f; }

            u32 bq[2][4];
            ldsm4(bq[0], kb8[0] + np * 4096);
#pragma unroll
            for (int ks = 0; ks < 8; ++ks) {
                if (ks < 7) ldsm4(bq[(ks + 1) & 1], kb8[ks + 1] + np * 4096);
                mma16816(S0, qf[ks], bq[ks & 1][0], bq[ks & 1][1]);
                mma16816(S1, qf[ks], bq[ks & 1][2], bq[ks & 1][3]);
            }

            if (interior) {
                const float cb0 = cj + snt[2 * np] - rb0;
                const float cb1 = cj + snt[2 * np + 1] - rb0;
                S0[0] = S0[0] * kscale2 + cb0;
                S0[1] = S0[1] * kscale2 + (cb0 + slope2);
                S0[2] = S0[2] * kscale2 + (cb0 - d8);
                S0[3] = S0[3] * kscale2 + (cb0 + slope2 - d8);
                S1[0] = S1[0] * kscale2 + cb1;
                S1[1] = S1[1] * kscale2 + (cb1 + slope2);
                S1[2] = S1[2] * kscale2 + (cb1 - d8);
                S1[3] = S1[3] * kscale2 + (cb1 + slope2 - d8);
            } else {
#pragma unroll
                for (int t = 0; t < 2; ++t) {
                    float* Sv = t ? S1 : S0;
                    const int c0 = j * 64 + 8 * (2 * np + t) + 2 * (lane & 3);
#pragma unroll
                    for (int e = 0; e < 2; ++e) {
                        const int d0 = c0 + e - rowg0;
                        float v0 = Sv[e] * kscale2 + slope2 * (float)d0;
                        Sv[e] = (d0 > 0) ? -1e6f : v0;
                        const int d1 = c0 + e - rowg1;
                        float v1 = Sv[2 + e] * kscale2 + slope2 * (float)d1;
                        Sv[2 + e] = (d1 > 0) ? -1e6f : v1;
                    }
                }
            }
            m0 = fmaxf(m0, fmaxf(fmaxf(S0[0], S0[1]), fmaxf(S1[0], S1[1])));
            m1 = fmaxf(m1, fmaxf(fmaxf(S0[2], S0[3]), fmaxf(S1[2], S1[3])));
        }

        // ---- online softmax (rows inside quad: shfl_xor 1,2) ----
        m0 = fmaxf(m0, __shfl_xor_sync(0xffffffffu, m0, 1));
        m0 = fmaxf(m0, __shfl_xor_sync(0xffffffffu, m0, 2));
        m1 = fmaxf(m1, __shfl_xor_sync(0xffffffffu, m1, 1));
        m1 = fmaxf(m1, __shfl_xor_sync(0xffffffffu, m1, 2));

        const float mn0 = fmaxf(mrun0, m0);
        const float mn1 = fmaxf(mrun1, m1);
        const float corr0 = ex2(mrun0 - mn0);
        const float corr1 = ex2(mrun1 - mn1);
        mrun0 = mn0; mrun1 = mn1;

        float ps0 = 0.f, ps1 = 0.f;
#pragma unroll
        for (int nt = 0; nt < 8; ++nt) {
            S[nt][0] = ex2(S[nt][0] - mn0); ps0 += S[nt][0];
            S[nt][1] = ex2(S[nt][1] - mn0); ps0 += S[nt][1];
            S[nt][2] = ex2(S[nt][2] - mn1); ps1 += S[nt][2];
            S[nt][3] = ex2(S[nt][3] - mn1); ps1 += S[nt][3];
        }
        ps0 += __shfl_xor_sync(0xffffffffu, ps0, 1);
        ps0 += __shfl_xor_sync(0xffffffffu, ps0, 2);
        ps1 += __shfl_xor_sync(0xffffffffu, ps1, 1);
        ps1 += __shfl_xor_sync(0xffffffffu, ps1, 2);
        lrun0 = lrun0 * corr0 + ps0;
        lrun1 = lrun1 * corr1 + ps1;

#pragma unroll
        for (int nt = 0; nt < 16; ++nt) {
            O[nt][0] *= corr0; O[nt][1] *= corr0;
            O[nt][2] *= corr1; O[nt][3] *= corr1;
        }

        // ---- O += P V (pipelined; P frags straight from S regs) ----
        const u32 vA = sb + KB_OFF + p * 32768 + 16384 + vAoff;
        u32 vb8[8];
#pragma unroll
        for (int np = 0; np < 8; ++np) vb8[np] = (vA + np * 32) ^ xsw;

        u32 bv[2][4];
        ldsm4t(bv[0], vb8[0]);
#pragma unroll
        for (int ks = 0; ks < 4; ++ks) {
            u32 pf[4];
            pf[0] = packh2(S[2 * ks][0],     S[2 * ks][1]);
            pf[1] = packh2(S[2 * ks][2],     S[2 * ks][3]);
            pf[2] = packh2(S[2 * ks + 1][0], S[2 * ks + 1][1]);
            pf[3] = packh2(S[2 * ks + 1][2], S[2 * ks + 1][3]);
#pragma unroll
            for (int np = 0; np < 8; ++np) {
                const int cur = (ks * 8 + np) & 1;
                const u32 nxt = (np < 7) ? (vb8[np + 1] + ks * 4096)
                                         : (vb8[0] + ((ks < 3) ? (ks + 1) * 4096 : 0));
                ldsm4t(bv[cur ^ 1], nxt);
                mma16816(O[2 * np],     pf, bv[cur][0], bv[cur][1]);
                mma16816(O[2 * np + 1], pf, bv[cur][2], bv[cur][3]);
            }
        }
    }

    // ---- epilogue: normalize + store ----
    const float inv0 = __fdividef(1.0f, lrun0);
    const float inv1 = __fdividef(1.0f, lrun1);
    float* o0 = gout + bhoff + (size_t)rowg0 * Dc;
    float* o1 = gout + bhoff + (size_t)rowg1 * Dc;
#pragma unroll
    for (int nt = 0; nt < 16; ++nt) {
        const int col = 8 * nt + 2 * (lane & 3);
        *(float2*)(o0 + col) = make_float2(O[nt][0] * inv0, O[nt][1] * inv0);
        *(float2*)(o1 + col) = make_float2(O[nt][2] * inv1, O[nt][3] * inv1);
    }
}

extern "C" void kernel_launch(void* const* d_in, const int* in_sizes, int n_in,
                              void* d_out, int out_size) {
    (void)in_sizes; (void)n_in; (void)out_size;
    const float* q = (const float*)d_in[0];
    const float* k = (const float*)d_in[1];
    const float* v = (const float*)d_in[2];
    // d_in[3] = mask: known causal tril, handled analytically in-kernel.
    float* out = (float*)d_out;

    cvt_kernel<<<24576, 256>>>(q, k, v);

    cudaFuncSetAttribute(attn_hmma_kernel,
                         cudaFuncAttributeMaxDynamicSharedMemorySize, SMEM_BYTES);
    dim3 grid(2 * Hc, Sc / BM);   // (B*H, 16 q-tiles)
    attn_hmma_kernel<<<grid, NT, SMEM_BYTES>>>(out);
}

// round 10
// speedup vs baseline: 1.1381x; 1.1381x over previous
#include <cuda_runtime.h>
#include <cuda_fp16.h>
#include <cstdint>

// Causal attention + ALiBi, B=2 H=16 S=2048 D=128, fp32 in/out.
// Warp-level HMMA flash attention, single-pass fp16 (m16n8k16.f32.f16.f16.f32).
// R10: 2 CTAs/SM with a true <=128-reg body: Q fragments streamed from smem
//      (ks-outer QK), no cached address arrays, 2-buffer K/V ring.

constexpr int Hc = 16;
constexpr int Sc = 2048;
constexpr int Dc = 128;
constexpr int BM = 128;
constexpr int BN = 64;
constexpr int NT = 256;
constexpr int BHSD = 2 * 16 * 2048 * 128;   // 8388608

// ---- device scratch: fp16 copies (row-major, same layout as inputs) ----
__device__ __half g_qf[BHSD];
__device__ __half g_kf[BHSD];
__device__ __half g_vf[BHSD];

// ---- smem byte offsets (rows of 256B = 128 fp16, XOR-swizzled) ----
constexpr int Q_OFF = 0;           // Q [128 m][128 k] fp16 (32768 B), resident
constexpr int KB_OFF = 32768;      // 2 bufs, 32768 B each (K +0, V +16384)
constexpr int SMEM_BYTES = 98304;  // 96 KB -> 2 CTAs/SM

typedef uint32_t u32;

__device__ __forceinline__ u32 smem_u32(const void* p) {
    u32 a;
    asm("{ .reg .u64 t; cvta.to.shared.u64 t, %1; cvt.u32.u64 %0, t; }" : "=r"(a) : "l"(p));
    return a;
}
__device__ __forceinline__ void cp16(u32 dst, const void* src) {
    asm volatile("cp.async.cg.shared.global [%0], [%1], 16;" :: "r"(dst), "l"(src));
}
__device__ __forceinline__ float ex2(float x) {
    float y; asm("ex2.approx.f32 %0, %1;" : "=f"(y) : "f"(x)); return y;
}
__device__ __forceinline__ void ldsm4(u32* r, u32 a) {
    asm volatile("ldmatrix.sync.aligned.m8n8.x4.shared.b16 {%0,%1,%2,%3}, [%4];"
                 : "=r"(r[0]), "=r"(r[1]), "=r"(r[2]), "=r"(r[3]) : "r"(a));
}
__device__ __forceinline__ void ldsm4t(u32* r, u32 a) {
    asm volatile("ldmatrix.sync.aligned.m8n8.x4.trans.shared.b16 {%0,%1,%2,%3}, [%4];"
                 : "=r"(r[0]), "=r"(r[1]), "=r"(r[2]), "=r"(r[3]) : "r"(a));
}
// Non-volatile: pure register op, ptxas may interleave freely.
__device__ __forceinline__ void mma16816(float* c, const u32* a, u32 b0, u32 b1) {
    asm("mma.sync.aligned.m16n8k16.row.col.f32.f16.f16.f32 "
        "{%0,%1,%2,%3}, {%4,%5,%6,%7}, {%8,%9}, {%0,%1,%2,%3};"
        : "+f"(c[0]), "+f"(c[1]), "+f"(c[2]), "+f"(c[3])
        : "r"(a[0]), "r"(a[1]), "r"(a[2]), "r"(a[3]), "r"(b0), "r"(b1));
}
__device__ __forceinline__ u32 packh2(float a, float b) {
    __half2 h = __floats2half2_rn(a, b);
    return *(u32*)&h;
}

// =================== conversion kernel (fp32 -> fp16) ===================
__global__ void __launch_bounds__(256) cvt_kernel(const float* __restrict__ q,
                                                  const float* __restrict__ k,
                                                  const float* __restrict__ v) {
    int t = blockIdx.x * 256 + threadIdx.x;      // 24576*256 = 3 * 2097152 float4s
    const float* src;
    __half* dst;
    int i;
    if (t < 2097152)      { src = q; dst = g_qf; i = t; }
    else if (t < 4194304) { src = k; dst = g_kf; i = t - 2097152; }
    else                  { src = v; dst = g_vf; i = t - 4194304; }
    float4 x = ((const float4*)src)[i];
    uint2 w;
    w.x = packh2(x.x, x.y);
    w.y = packh2(x.z, x.w);
    ((uint2*)dst)[i] = w;
}

// =================== main attention kernel ===================

// cp.async loader for one K/V fp16 tile: 64 rows x 128 fp16 each.
__device__ __forceinline__ void load_kv(const __half* kf, const __half* vf,
                                        u32 dst, int tid) {
#pragma unroll
    for (int i = 0; i < 4; ++i) {
        const int idx = i * 256 + tid;
        const int row = idx >> 4, g = idx & 15;
        const u32 off = row * 256 + (((u32)(g ^ (row & 7))) << 4);
        const int so = row * Dc + g * 8;
        cp16(dst + off, kf + so);
        cp16(dst + 16384 + off, vf + so);
    }
}

__global__ void __launch_bounds__(NT, 2)
attn_hmma_kernel(float* __restrict__ gout) {
    extern __shared__ char smc[];
    const u32 sb = smem_u32(smc);
    const int tid = threadIdx.x;
    const int lane = tid & 31;
    const int w = tid >> 5;

    const int bh = blockIdx.x;
    const int qtile = 15 - (int)blockIdx.y;   // heavy tiles first
    const int h = bh & (Hc - 1);
    const int q0 = qtile * BM;
    const int jmax = 2 * qtile + 1;           // >= 1 always

    const float LOG2E = 1.4426950408889634f;
    const float kscale2 = LOG2E * 0.08838834764831845f;   // log2e / sqrt(128)
    const float slope2 = exp2f(-0.5f * (float)(h + 1)) * LOG2E;

    const size_t bhoff = (size_t)bh * Sc * Dc;

    // ---- prologue: stage Q (swizzled, stays resident) + K/V tile 0 ----
    {
        const __half* qf = g_qf + bhoff + (size_t)q0 * Dc;
#pragma unroll
        for (int i = 0; i < 8; ++i) {
            const int idx = i * 256 + tid;
            const int row = idx >> 4, g = idx & 15;
            const u32 off = row * 256 + (((u32)(g ^ (row & 7))) << 4);
            cp16(sb + Q_OFF + off, qf + row * Dc + g * 8);
        }
        load_kv(g_kf + bhoff, g_vf + bhoff, sb + KB_OFF, tid);
    }
    asm volatile("cp.async.commit_group;");
    asm volatile("cp.async.wait_group 0;");
    __syncthreads();

    // ---- per-lane ldmatrix address bases (XOR folded in; +np*4096 commutes) ----
    const u32 xsw = ((u32)(lane & 7)) << 4;
    const int qrow = 16 * w + (lane & 7) + ((lane >> 3) & 1) * 8;
    const u32 qA = (sb + Q_OFF + qrow * 256 + (((u32)(lane >> 4)) << 4));
    const int krow = (lane & 7) + ((lane >> 4) & 1) * 8;
    const u32 kAoff = krow * 256 + (((u32)((lane >> 3) & 1)) << 4);
    const int vrow = (lane & 7) + ((lane >> 3) & 1) * 8;
    const u32 vAoff = vrow * 256 + (((u32)(lane >> 4)) << 4);

    // ---- running state ----
    float O[16][4];
#pragma unroll
    for (int nt = 0; nt < 16; ++nt)
#pragma unroll
        for (int e = 0; e < 4; ++e) O[nt][e] = 0.f;
    float mrun0 = -1e30f, mrun1 = -1e30f, lrun0 = 0.f, lrun1 = 0.f;

    const int rowg0 = q0 + 16 * w + (lane >> 2);
    const int rowg1 = rowg0 + 8;
    const float rb0 = slope2 * (float)rowg0;
    const float d8 = slope2 * 8.0f;
    const float cstep = slope2 * (float)(2 * (lane & 3));

    for (int j = 0; j <= jmax; ++j) {
        const int p = j & 1;

        __syncthreads();   // prior-iter reads of buffer p^1 complete
        if (j < jmax) {
            const size_t toff = bhoff + (size_t)(j + 1) * BN * Dc;
            load_kv(g_kf + toff, g_vf + toff, sb + KB_OFF + (p ^ 1) * 32768, tid);
        }
        asm volatile("cp.async.commit_group;");
        asm volatile("cp.async.wait_group 1;");   // buffer p's group complete
        __syncthreads();                           // publish buffer p

        // ---- S = Q K^T, ks-outer; Q streamed from smem (ping-pong) ----
        float S[8][4];
#pragma unroll
        for (int nt = 0; nt < 8; ++nt)
#pragma unroll
            for (int e = 0; e < 4; ++e) S[nt][e] = 0.f;

        const u32 kA = sb + KB_OFF + p * 32768 + kAoff;

        u32 qq[2][4], bq[2][4];
        ldsm4(qq[0], qA ^ xsw);
        ldsm4(bq[0], kA ^ xsw);
#pragma unroll
        for (int ks = 0; ks < 8; ++ks) {
            const u32 kbase = (kA + ks * 32) ^ xsw;
            if (ks < 7) ldsm4(qq[(ks + 1) & 1], (qA + (ks + 1) * 32) ^ xsw);
            const u32* aq = qq[ks & 1];
#pragma unroll
            for (int np = 0; np < 4; ++np) {
                const int cur = (ks * 4 + np) & 1;
                const u32 nxt = (np < 3) ? (kbase + (np + 1) * 4096)
                                         : (((kA + (ks + 1) * 32) ^ xsw));
                if (ks < 7 || np < 3) ldsm4(bq[cur ^ 1], nxt);
                mma16816(S[2 * np],     aq, bq[cur][0], bq[cur][1]);
                mma16816(S[2 * np + 1], aq, bq[cur][2], bq[cur][3]);
            }
        }

        // ---- scale + alibi (+ causal mask on edge tiles) ----
        if (j < jmax - 1) {
            const float cj = slope2 * (float)(j * 64) + cstep - rb0;
#pragma unroll
            for (int nt = 0; nt < 8; ++nt) {
                const float cb = cj + slope2 * (float)(8 * nt);
                S[nt][0] = S[nt][0] * kscale2 + cb;
                S[nt][1] = S[nt][1] * kscale2 + (cb + slope2);
                S[nt][2] = S[nt][2] * kscale2 + (cb - d8);
                S[nt][3] = S[nt][3] * kscale2 + (cb + slope2 - d8);
            }
        } else {
#pragma unroll
            for (int nt = 0; nt < 8; ++nt) {
                const int c0 = j * 64 + 8 * nt + 2 * (lane & 3);
#pragma unroll
                for (int e = 0; e < 2; ++e) {
                    const int d0 = c0 + e - rowg0;
                    float v0 = S[nt][e] * kscale2 + slope2 * (float)d0;
                    S[nt][e] = (d0 > 0) ? -1e6f : v0;
                    const int d1 = c0 + e - rowg1;
                    float v1 = S[nt][2 + e] * kscale2 + slope2 * (float)d1;
                    S[nt][2 + e] = (d1 > 0) ? -1e6f : v1;
                }
            }
        }

        // ---- online softmax (rows inside quad: shfl_xor 1,2) ----
        float m0 = -1e30f, m1 = -1e30f;
#pragma unroll
        for (int nt = 0; nt < 8; ++nt) {
            m0 = fmaxf(m0, fmaxf(S[nt][0], S[nt][1]));
            m1 = fmaxf(m1, fmaxf(S[nt][2], S[nt][3]));
        }
        m0 = fmaxf(m0, __shfl_xor_sync(0xffffffffu, m0, 1));
        m0 = fmaxf(m0, __shfl_xor_sync(0xffffffffu, m0, 2));
        m1 = fmaxf(m1, __shfl_xor_sync(0xffffffffu, m1, 1));
        m1 = fmaxf(m1, __shfl_xor_sync(0xffffffffu, m1, 2));

        const float mn0 = fmaxf(mrun0, m0);
        const float mn1 = fmaxf(mrun1, m1);
        const float corr0 = ex2(mrun0 - mn0);
        const float corr1 = ex2(mrun1 - mn1);
        mrun0 = mn0; mrun1 = mn1;

        float ps0 = 0.f, ps1 = 0.f;
#pragma unroll
        for (int nt = 0; nt < 8; ++nt) {
            S[nt][0] = ex2(S[nt][0] - mn0); ps0 += S[nt][0];
            S[nt][1] = ex2(S[nt][1] - mn0); ps0 += S[nt][1];
            S[nt][2] = ex2(S[nt][2] - mn1); ps1 += S[nt][2];
            S[nt][3] = ex2(S[nt][3] - mn1); ps1 += S[nt][3];
        }
        ps0 += __shfl_xor_sync(0xffffffffu, ps0, 1);
        ps0 += __shfl_xor_sync(0xffffffffu, ps0, 2);
        ps1 += __shfl_xor_sync(0xffffffffu, ps1, 1);
        ps1 += __shfl_xor_sync(0xffffffffu, ps1, 2);
        lrun0 = lrun0 * corr0 + ps0;
        lrun1 = lrun1 * corr1 + ps1;

#pragma unroll
        for (int nt = 0; nt < 16; ++nt) {
            O[nt][0] *= corr0; O[nt][1] *= corr0;
            O[nt][2] *= corr1; O[nt][3] *= corr1;
        }

        // ---- O += P V (pipelined; P frags straight from S regs) ----
        const u32 vA = sb + KB_OFF + p * 32768 + 16384 + vAoff;
        u32 bv[2][4];
        ldsm4t(bv[0], vA ^ xsw);
#pragma unroll
        for (int ks = 0; ks < 4; ++ks) {
            const u32 vbase = (vA ^ xsw) + ks * 4096;
            u32 pf[4];
            pf[0] = packh2(S[2 * ks][0],     S[2 * ks][1]);
            pf[1] = packh2(S[2 * ks][2],     S[2 * ks][3]);
            pf[2] = packh2(S[2 * ks + 1][0], S[2 * ks + 1][1]);
            pf[3] = packh2(S[2 * ks + 1][2], S[2 * ks + 1][3]);
#pragma unroll
            for (int np = 0; np < 8; ++np) {
                const int cur = (ks * 8 + np) & 1;
                const u32 nxt = (np < 7) ? ((vA + (np + 1) * 32) ^ xsw) + ks * 4096
                                         : ((vA ^ xsw) + (ks + 1) * 4096);
                if (ks < 3 || np < 7) ldsm4t(bv[cur ^ 1], nxt);
                mma16816(O[2 * np],     pf, bv[cur][0], bv[cur][1]);
                mma16816(O[2 * np + 1], pf, bv[cur][2], bv[cur][3]);
            }
        }
    }

    // ---- epilogue: normalize + store ----
    const float inv0 = __fdividef(1.0f, lrun0);
    const float inv1 = __fdividef(1.0f, lrun1);
    float* o0 = gout + bhoff + (size_t)rowg0 * Dc;
    float* o1 = gout + bhoff + (size_t)rowg1 * Dc;
#pragma unroll
    for (int nt = 0; nt < 16; ++nt) {
        const int col = 8 * nt + 2 * (lane & 3);
        *(float2*)(o0 + col) = make_float2(O[nt][0] * inv0, O[nt][1] * inv0);
        *(float2*)(o1 + col) = make_float2(O[nt][2] * inv1, O[nt][3] * inv1);
    }
}

extern "C" void kernel_launch(void* const* d_in, const int* in_sizes, int n_in,
                              void* d_out, int out_size) {
    (void)in_sizes; (void)n_in; (void)out_size;
    const float* q = (const float*)d_in[0];
    const float* k = (const float*)d_in[1];
    const float* v = (const float*)d_in[2];
    // d_in[3] = mask: known causal tril, handled analytically in-kernel.
    float* out = (float*)d_out;

    cvt_kernel<<<24576, 256>>>(q, k, v);

    cudaFuncSetAttribute(attn_hmma_kernel,
                         cudaFuncAttributeMaxDynamicSharedMemorySize, SMEM_BYTES);
    dim3 grid(2 * Hc, Sc / BM);   // (B*H, 16 q-tiles)
    attn_hmma_kernel<<<grid, NT, SMEM_BYTES>>>(out);
}

// round 13
// speedup vs baseline: 1.3288x; 1.1675x over previous
#include <cuda_runtime.h>
#include <cuda_fp16.h>
#include <cstdint>

// Causal attention + ALiBi, B=2 H=16 S=2048 D=128, fp32 in/out.
// Warp-level HMMA flash attention, single-pass fp16 (m16n8k16.f32.f16.f16.f32).
// R12: mbarrier producer/consumer ring, 4 KV slots, cp.async arrives use
//      .noinc (R11 hang fix). No __syncthreads in the main loop -> warps can
//      skew up to 2 iterations; softmax of one warp overlaps MMAs of another.

constexpr int Hc = 16;
constexpr int Sc = 2048;
constexpr int Dc = 128;
constexpr int BM = 128;
constexpr int BN = 64;
constexpr int NT = 256;
constexpr int BHSD = 2 * 16 * 2048 * 128;   // 8388608

// ---- device scratch: fp16 copies (row-major, same layout as inputs) ----
__device__ __half g_qf[BHSD];
__device__ __half g_kf[BHSD];
__device__ __half g_vf[BHSD];

// ---- smem byte offsets (rows of 256B = 128 fp16, XOR-swizzled) ----
constexpr int Q_OFF = 0;            // Q [128 m][128 k] fp16 (32768 B) — staging
constexpr int KB_OFF = 32768;       // 4 slots, 32768 B each (K +0, V +16384)
constexpr int BAR_F = 163840;       // full mbarriers, 4 x 8 B
constexpr int BAR_E = 163840 + 32;  // empty mbarriers, 4 x 8 B
constexpr int SMEM_BYTES = 163904;

typedef uint32_t u32;

__device__ __forceinline__ u32 smem_u32(const void* p) {
    u32 a;
    asm("{ .reg .u64 t; cvta.to.shared.u64 t, %1; cvt.u32.u64 %0, t; }" : "=r"(a) : "l"(p));
    return a;
}
__device__ __forceinline__ void cp16(u32 dst, const void* src) {
    asm volatile("cp.async.cg.shared.global [%0], [%1], 16;" :: "r"(dst), "l"(src));
}
__device__ __forceinline__ float ex2(float x) {
    float y; asm("ex2.approx.f32 %0, %1;" : "=f"(y) : "f"(x)); return y;
}
__device__ __forceinline__ void ldsm4(u32* r, u32 a) {
    asm volatile("ldmatrix.sync.aligned.m8n8.x4.shared.b16 {%0,%1,%2,%3}, [%4];"
                 : "=r"(r[0]), "=r"(r[1]), "=r"(r[2]), "=r"(r[3]) : "r"(a));
}
__device__ __forceinline__ void ldsm4t(u32* r, u32 a) {
    asm volatile("ldmatrix.sync.aligned.m8n8.x4.trans.shared.b16 {%0,%1,%2,%3}, [%4];"
                 : "=r"(r[0]), "=r"(r[1]), "=r"(r[2]), "=r"(r[3]) : "r"(a));
}
// Non-volatile: pure register op, ptxas may interleave freely.
__device__ __forceinline__ void mma16816(float* c, const u32* a, u32 b0, u32 b1) {
    asm("mma.sync.aligned.m16n8k16.row.col.f32.f16.f16.f32 "
        "{%0,%1,%2,%3}, {%4,%5,%6,%7}, {%8,%9}, {%0,%1,%2,%3};"
        : "+f"(c[0]), "+f"(c[1]), "+f"(c[2]), "+f"(c[3])
        : "r"(a[0]), "r"(a[1]), "r"(a[2]), "r"(a[3]), "r"(b0), "r"(b1));
}
__device__ __forceinline__ u32 packh2(float a, float b) {
    __half2 h = __floats2half2_rn(a, b);
    return *(u32*)&h;
}

// ---- mbarrier helpers ----
__device__ __forceinline__ void mb_init(u32 a, u32 cnt) {
    asm volatile("mbarrier.init.shared.b64 [%0], %1;" :: "r"(a), "r"(cnt) : "memory");
}
__device__ __forceinline__ void mb_arrive(u32 a) {
    asm volatile("mbarrier.arrive.shared.b64 _, [%0];" :: "r"(a) : "memory");
}
// .noinc: the completion-arrive consumes one unit of the initialized count.
__device__ __forceinline__ void mb_cpasync_arrive(u32 a) {
    asm volatile("cp.async.mbarrier.arrive.noinc.shared.b64 [%0];" :: "r"(a) : "memory");
}
__device__ __forceinline__ void mb_wait(u32 a, u32 parity) {
    asm volatile(
        "{\n\t.reg .pred P1;\n\t"
        "WL_%=:\n\t"
        "mbarrier.try_wait.parity.shared.b64 P1, [%0], %1, 0x989680;\n\t"
        "@P1 bra.uni WD_%=;\n\t"
        "bra.uni WL_%=;\n\t"
        "WD_%=:\n\t}"
        :: "r"(a), "r"(parity) : "memory");
}

// =================== conversion kernel (fp32 -> fp16) ===================
__global__ void __launch_bounds__(256) cvt_kernel(const float* __restrict__ q,
                                                  const float* __restrict__ k,
                                                  const float* __restrict__ v) {
    int t = blockIdx.x * 256 + threadIdx.x;      // 24576*256 = 3 * 2097152 float4s
    const float* src;
    __half* dst;
    int i;
    if (t < 2097152)      { src = q; dst = g_qf; i = t; }
    else if (t < 4194304) { src = k; dst = g_kf; i = t - 2097152; }
    else                  { src = v; dst = g_vf; i = t - 4194304; }
    float4 x = ((const float4*)src)[i];
    uint2 w;
    w.x = packh2(x.x, x.y);
    w.y = packh2(x.z, x.w);
    ((uint2*)dst)[i] = w;
}

// =================== main attention kernel ===================

// cp.async loader for one K/V fp16 tile: 64 rows x 128 fp16 each.
__device__ __forceinline__ void load_kv(const __half* kf, const __half* vf,
                                        u32 dst, int tid) {
#pragma unroll
    for (int i = 0; i < 4; ++i) {
        const int idx = i * 256 + tid;
        const int row = idx >> 4, g = idx & 15;
        const u32 off = row * 256 + (((u32)(g ^ (row & 7))) << 4);
        const int so = row * Dc + g * 8;
        cp16(dst + off, kf + so);
        cp16(dst + 16384 + off, vf + so);
    }
}

__global__ void __launch_bounds__(NT, 1)
attn_hmma_kernel(float* __restrict__ gout) {
    extern __shared__ char smc[];
    const u32 sb = smem_u32(smc);
    const int tid = threadIdx.x;
    const int lane = tid & 31;
    const int w = tid >> 5;

    const int bh = blockIdx.x;
    const int qtile = 15 - (int)blockIdx.y;   // heavy tiles first
    const int h = bh & (Hc - 1);
    const int q0 = qtile * BM;
    const int jmax = 2 * qtile + 1;           // >= 1 always

    const float LOG2E = 1.4426950408889634f;
    const float kscale2 = LOG2E * 0.08838834764831845f;   // log2e / sqrt(128)
    const float slope2 = exp2f(-0.5f * (float)(h + 1)) * LOG2E;

    const size_t bhoff = (size_t)bh * Sc * Dc;

    // ---- init barriers, then publish before any arrive/wait ----
    if (tid == 0) {
#pragma unroll
        for (int s = 0; s < 4; ++s) {
            mb_init(sb + BAR_F + s * 8, NT);
            mb_init(sb + BAR_E + s * 8, NT);
        }
    }
    // Q cp.asyncs issued before the sync (they don't touch barriers)
    {
        const __half* qf = g_qf + bhoff + (size_t)q0 * Dc;
#pragma unroll
        for (int i = 0; i < 8; ++i) {
            const int idx = i * 256 + tid;
            const int row = idx >> 4, g = idx & 15;
            const u32 off = row * 256 + (((u32)(g ^ (row & 7))) << 4);
            cp16(sb + Q_OFF + off, qf + row * Dc + g * 8);
        }
    }
    __syncthreads();   // barriers initialized

    // ---- prologue produces: slots 0 (j=0) and 1 (j=1); jmax >= 1 always ----
    load_kv(g_kf + bhoff, g_vf + bhoff, sb + KB_OFF, tid);
    mb_cpasync_arrive(sb + BAR_F + 0 * 8);   // fires when Q + slot0 loads done
    load_kv(g_kf + bhoff + (size_t)BN * Dc, g_vf + bhoff + (size_t)BN * Dc,
            sb + KB_OFF + 32768, tid);
    mb_cpasync_arrive(sb + BAR_F + 1 * 8);

    // ---- per-lane ldmatrix address pieces ----
    const u32 xsw = ((u32)(lane & 7)) << 4;
    const int qrow = 16 * w + (lane & 7) + ((lane >> 3) & 1) * 8;
    const u32 qA = sb + Q_OFF + qrow * 256 + (((u32)(lane >> 4)) << 4);
    const int krow = (lane & 7) + ((lane >> 4) & 1) * 8;
    const u32 kAoff = krow * 256 + (((u32)((lane >> 3) & 1)) << 4);
    const int vrow = (lane & 7) + ((lane >> 3) & 1) * 8;
    const u32 vAoff = vrow * 256 + (((u32)(lane >> 4)) << 4);

    // ---- wait slot0 full (covers Q too), hoist Q fragments ----
    mb_wait(sb + BAR_F + 0 * 8, 0);
    u32 qf[8][4];
#pragma unroll
    for (int ks = 0; ks < 8; ++ks) ldsm4(qf[ks], (qA + ks * 32) ^ xsw);

    // ---- running state ----
    float O[16][4];
#pragma unroll
    for (int nt = 0; nt < 16; ++nt)
#pragma unroll
        for (int e = 0; e < 4; ++e) O[nt][e] = 0.f;
    float mrun0 = -1e30f, mrun1 = -1e30f, lrun0 = 0.f, lrun1 = 0.f;

    const int rowg0 = q0 + 16 * w + (lane >> 2);
    const int rowg1 = rowg0 + 8;
    const float rb0 = slope2 * (float)rowg0;
    const float d8 = slope2 * 8.0f;
    const float cstep = slope2 * (float)(2 * (lane & 3));
    float snt[8];
#pragma unroll
    for (int nt = 0; nt < 8; ++nt) snt[nt] = slope2 * (float)(8 * nt);

    // producer cursor: prologue produced slots 0,1 -> next stage 2.
    // First empty-wait of each slot (use #0) must pass immediately -> phase 1.
    int pstage = 2, pphase = 1;
    // consumer cursor: slot0 use #0 -> phase 0.
    int cstage = 0, cphase = 0;

    for (int j = 0; j <= jmax; ++j) {
        // ---- produce slot for j+2 (uniform branch across CTA) ----
        if (j + 2 <= jmax) {
            mb_wait(sb + BAR_E + pstage * 8, (u32)pphase);
            const size_t toff = bhoff + (size_t)(j + 2) * BN * Dc;
            load_kv(g_kf + toff, g_vf + toff, sb + KB_OFF + pstage * 32768, tid);
            mb_cpasync_arrive(sb + BAR_F + pstage * 8);
            if (++pstage == 4) { pstage = 0; pphase ^= 1; }
        }

        // ---- consume slot for j ----
        mb_wait(sb + BAR_F + cstage * 8, (u32)cphase);
        const u32 kvbase = sb + KB_OFF + cstage * 32768;

        // ---- S = Q K^T (pipelined ldsm -> mma) ----
        float S[8][4];
#pragma unroll
        for (int nt = 0; nt < 8; ++nt)
#pragma unroll
            for (int e = 0; e < 4; ++e) S[nt][e] = 0.f;

        const u32 kA = kvbase + kAoff;
        u32 kb8[8];
#pragma unroll
        for (int ks = 0; ks < 8; ++ks) kb8[ks] = (kA + ks * 32) ^ xsw;

        u32 bq[2][4];
        ldsm4(bq[0], kb8[0]);
#pragma unroll
        for (int ks = 0; ks < 8; ++ks) {
#pragma unroll
            for (int np = 0; np < 4; ++np) {
                const int cur = (ks * 4 + np) & 1;
                const u32 nxt = (np < 3) ? (kb8[ks] + (np + 1) * 4096)
                                         : ((ks < 7) ? kb8[ks + 1] : kb8[0]);
                ldsm4(bq[cur ^ 1], nxt);
                mma16816(S[2 * np],     qf[ks], bq[cur][0], bq[cur][1]);
                mma16816(S[2 * np + 1], qf[ks], bq[cur][2], bq[cur][3]);
            }
        }

        // ---- scale + alibi (+ causal mask on edge tiles) ----
        if (j < jmax - 1) {
            const float cj = slope2 * (float)(j * 64) + cstep;
#pragma unroll
            for (int nt = 0; nt < 8; ++nt) {
                const float cb = cj + snt[nt] - rb0;
                S[nt][0] = S[nt][0] * kscale2 + cb;
                S[nt][1] = S[nt][1] * kscale2 + (cb + slope2);
                S[nt][2] = S[nt][2] * kscale2 + (cb - d8);
                S[nt][3] = S[nt][3] * kscale2 + (cb + slope2 - d8);
            }
        } else {
#pragma unroll
            for (int nt = 0; nt < 8; ++nt) {
                const int c0 = j * 64 + 8 * nt + 2 * (lane & 3);
#pragma unroll
                for (int e = 0; e < 2; ++e) {
                    const int d0 = c0 + e - rowg0;
                    float v0 = S[nt][e] * kscale2 + slope2 * (float)d0;
                    S[nt][e] = (d0 > 0) ? -1e6f : v0;
                    const int d1 = c0 + e - rowg1;
                    float v1 = S[nt][2 + e] * kscale2 + slope2 * (float)d1;
                    S[nt][2 + e] = (d1 > 0) ? -1e6f : v1;
                }
            }
        }

        // ---- online softmax (rows inside quad: shfl_xor 1,2) ----
        float m0 = -1e30f, m1 = -1e30f;
#pragma unroll
        for (int nt = 0; nt < 8; ++nt) {
            m0 = fmaxf(m0, fmaxf(S[nt][0], S[nt][1]));
            m1 = fmaxf(m1, fmaxf(S[nt][2], S[nt][3]));
        }
        m0 = fmaxf(m0, __shfl_xor_sync(0xffffffffu, m0, 1));
        m0 = fmaxf(m0, __shfl_xor_sync(0xffffffffu, m0, 2));
        m1 = fmaxf(m1, __shfl_xor_sync(0xffffffffu, m1, 1));
        m1 = fmaxf(m1, __shfl_xor_sync(0xffffffffu, m1, 2));

        const float mn0 = fmaxf(mrun0, m0);
        const float mn1 = fmaxf(mrun1, m1);
        const float corr0 = ex2(mrun0 - mn0);
        const float corr1 = ex2(mrun1 - mn1);
        mrun0 = mn0; mrun1 = mn1;

        float ps0 = 0.f, ps1 = 0.f;
#pragma unroll
        for (int nt = 0; nt < 8; ++nt) {
            S[nt][0] = ex2(S[nt][0] - mn0); ps0 += S[nt][0];
            S[nt][1] = ex2(S[nt][1] - mn0); ps0 += S[nt][1];
            S[nt][2] = ex2(S[nt][2] - mn1); ps1 += S[nt][2];
            S[nt][3] = ex2(S[nt][3] - mn1); ps1 += S[nt][3];
        }
        ps0 += __shfl_xor_sync(0xffffffffu, ps0, 1);
        ps0 += __shfl_xor_sync(0xffffffffu, ps0, 2);
        ps1 += __shfl_xor_sync(0xffffffffu, ps1, 1);
        ps1 += __shfl_xor_sync(0xffffffffu, ps1, 2);
        lrun0 = lrun0 * corr0 + ps0;
        lrun1 = lrun1 * corr1 + ps1;

#pragma unroll
        for (int nt = 0; nt < 16; ++nt) {
            O[nt][0] *= corr0; O[nt][1] *= corr0;
            O[nt][2] *= corr1; O[nt][3] *= corr1;
        }

        // ---- O += P V (pipelined; P frags straight from S regs) ----
        const u32 vA = kvbase + 16384 + vAoff;
        u32 vb8[8];
#pragma unroll
        for (int np = 0; np < 8; ++np) vb8[np] = (vA + np * 32) ^ xsw;

        u32 bv[2][4];
        ldsm4t(bv[0], vb8[0]);
#pragma unroll
        for (int ks = 0; ks < 4; ++ks) {
            u32 pf[4];
            pf[0] = packh2(S[2 * ks][0],     S[2 * ks][1]);
            pf[1] = packh2(S[2 * ks][2],     S[2 * ks][3]);
            pf[2] = packh2(S[2 * ks + 1][0], S[2 * ks + 1][1]);
            pf[3] = packh2(S[2 * ks + 1][2], S[2 * ks + 1][3]);
#pragma unroll
            for (int np = 0; np < 8; ++np) {
                const int cur = (ks * 8 + np) & 1;
                const u32 nxt = (np < 7) ? (vb8[np + 1] + ks * 4096)
                                         : (vb8[0] + ((ks < 3) ? (ks + 1) * 4096 : 0));
                ldsm4t(bv[cur ^ 1], nxt);
                mma16816(O[2 * np],     pf, bv[cur][0], bv[cur][1]);
                mma16816(O[2 * np + 1], pf, bv[cur][2], bv[cur][3]);
            }
        }

        // ---- release slot ----
        mb_arrive(sb + BAR_E + cstage * 8);
        if (++cstage == 4) { cstage = 0; cphase ^= 1; }
    }

    // ---- epilogue: normalize + store ----
    const float inv0 = __fdividef(1.0f, lrun0);
    const float inv1 = __fdividef(1.0f, lrun1);
    float* o0 = gout + bhoff + (size_t)rowg0 * Dc;
    float* o1 = gout + bhoff + (size_t)rowg1 * Dc;
#pragma unroll
    for (int nt = 0; nt < 16; ++nt) {
        const int col = 8 * nt + 2 * (lane & 3);
        *(float2*)(o0 + col) = make_float2(O[nt][0] * inv0, O[nt][1] * inv0);
        *(float2*)(o1 + col) = make_float2(O[nt][2] * inv1, O[nt][3] * inv1);
    }
}

extern "C" void kernel_launch(void* const* d_in, const int* in_sizes, int n_in,
                              void* d_out, int out_size) {
    (void)in_sizes; (void)n_in; (void)out_size;
    const float* q = (const float*)d_in[0];
    const float* k = (const float*)d_in[1];
    const float* v = (const float*)d_in[2];
    // d_in[3] = mask: known causal tril, handled analytically in-kernel.
    float* out = (float*)d_out;

    cvt_kernel<<<24576, 256>>>(q, k, v);

    cudaFuncSetAttribute(attn_hmma_kernel,
                         cudaFuncAttributeMaxDynamicSharedMemorySize, SMEM_BYTES);
    dim3 grid(2 * Hc, Sc / BM);   // (B*H, 16 q-tiles)
    attn_hmma_kernel<<<grid, NT, SMEM_BYTES>>>(out);
}